// round 1
// baseline (speedup 1.0000x reference)
#include <cuda_runtime.h>
#include <cstdint>

// ---------------- problem constants ----------------
#define BATCH   16
#define HH      56
#define WW      56
#define NPIX    (HH*WW)        // 3136
#define C       384
#define HEADS   8
#define HD      48
#define SRR     2
#define PH      (HH/SRR)       // 28
#define PW      (WW/SRR)       // 28
#define NP      (PH*PW)        // 784
#define BH      (BATCH*HEADS)  // 128
#define SCALE   0.14433756729740643f  // 48^-0.5
#define EPS     1e-5f

// ---------------- scratch (device globals; no allocation allowed) ----------------
__device__ float g_q[(size_t)BH * NP * HD];
__device__ float g_k[(size_t)BH * NP * HD];
__device__ float g_v[(size_t)BH * NP * HD];
__device__ float g_o[(size_t)BATCH * NP * C];
__device__ float g_y[(size_t)BATCH * NPIX * C];

// =====================================================================
// Kernel 1: QKV GEMM with fused strided avg-pool(1x1,stride 2) on A.
//   A[m, k] = x[b, pooled-pixel(i), k],  m = b*784 + i,  M = 12544
//   Bmat[j, k] = qkv_w[j, k],            N = 1152, K = 384
//   C[m, j] scattered to g_q/g_k/g_v in [bh][i][d] layout (+ bias).
// 64x64x16 tile, 256 threads, 4x4 per thread.
// =====================================================================
#define BM 64
#define BN 64
#define BK 16
__global__ __launch_bounds__(256) void qkv_gemm_kernel(
    const float* __restrict__ x, const float* __restrict__ w,
    const float* __restrict__ bias)
{
    __shared__ float As[BK][BM];
    __shared__ float Bs[BK][BN];

    const int tile_n = blockIdx.x * BN;
    const int tile_m = blockIdx.y * BM;
    const int tid = threadIdx.x;
    const int tx = tid & 15;        // 0..15
    const int ty = tid >> 4;        // 0..15

    // cooperative-load mapping: each thread loads 4 consecutive k of one row
    const int lrow = tid >> 2;           // 0..63
    const int lk   = (tid & 3) * 4;      // 0,4,8,12

    // A source pointer (strided subsample of x)
    const int m  = tile_m + lrow;
    const int b  = m / NP;
    const int i  = m - b * NP;
    const int hi = (i / PW) * SRR;
    const int wi = (i - (i / PW) * PW) * SRR;
    const float* a_src = x + ((size_t)b * NPIX + hi * WW + wi) * C;
    const float* b_src = w + (size_t)(tile_n + lrow) * C;

    float acc[4][4] = {};

    for (int k0 = 0; k0 < C; k0 += BK) {
        float4 av = *(const float4*)(a_src + k0 + lk);
        float4 bv = *(const float4*)(b_src + k0 + lk);
        As[lk+0][lrow] = av.x; As[lk+1][lrow] = av.y;
        As[lk+2][lrow] = av.z; As[lk+3][lrow] = av.w;
        Bs[lk+0][lrow] = bv.x; Bs[lk+1][lrow] = bv.y;
        Bs[lk+2][lrow] = bv.z; Bs[lk+3][lrow] = bv.w;
        __syncthreads();
        #pragma unroll
        for (int kk = 0; kk < BK; kk++) {
            float a[4], bb[4];
            #pragma unroll
            for (int t = 0; t < 4; t++) a[t]  = As[kk][ty*4 + t];
            #pragma unroll
            for (int t = 0; t < 4; t++) bb[t] = Bs[kk][tx*4 + t];
            #pragma unroll
            for (int ii = 0; ii < 4; ii++)
                #pragma unroll
                for (int jj = 0; jj < 4; jj++)
                    acc[ii][jj] += a[ii] * bb[jj];
        }
        __syncthreads();
    }

    // epilogue: bias + scatter into per-head q/k/v
    #pragma unroll
    for (int ii = 0; ii < 4; ii++) {
        const int gm = tile_m + ty*4 + ii;
        const int ob = gm / NP;
        const int oi = gm - ob * NP;
        #pragma unroll
        for (int jj = 0; jj < 4; jj++) {
            const int gj = tile_n + tx*4 + jj;
            const float val = acc[ii][jj] + bias[gj];
            const int which = gj / C;
            const int c2    = gj - which * C;
            const int head  = c2 / HD;
            const int d     = c2 - head * HD;
            const size_t idx = ((size_t)(ob * HEADS + head) * NP + oi) * HD + d;
            if (which == 0)      g_q[idx] = val;
            else if (which == 1) g_k[idx] = val;
            else                 g_v[idx] = val;
        }
    }
}

// =====================================================================
// Kernel 2: flash attention per (b,h). One q-row per thread, K/V tiles
// staged in smem (broadcast LDS), online softmax.
// grid = (ceil(784/128), 128), 128 threads.
// =====================================================================
#define TK 112
__global__ __launch_bounds__(128) void attn_kernel(float* __restrict__ o_out)
{
    __shared__ float Ks[TK][HD];
    __shared__ float Vs[TK][HD];

    const int bh = blockIdx.y;
    const int qi = blockIdx.x * 128 + threadIdx.x;
    const bool valid = (qi < NP);

    const float* kb = g_k + (size_t)bh * NP * HD;
    const float* vb = g_v + (size_t)bh * NP * HD;

    float qr[HD];
    if (valid) {
        const float* qp = g_q + ((size_t)bh * NP + qi) * HD;
        #pragma unroll
        for (int d = 0; d < HD; d += 4) {
            float4 t = *(const float4*)(qp + d);
            qr[d] = t.x; qr[d+1] = t.y; qr[d+2] = t.z; qr[d+3] = t.w;
        }
    }

    float mval = -1e30f, lsum = 0.f;
    float acc[HD] = {};

    for (int k0 = 0; k0 < NP; k0 += TK) {
        // cooperative tile load (float4)
        for (int idx = threadIdx.x; idx < TK * (HD/4); idx += 128) {
            const int r  = idx / (HD/4);
            const int d4 = (idx - r * (HD/4)) * 4;
            *(float4*)&Ks[r][d4] = *(const float4*)(kb + (size_t)(k0 + r) * HD + d4);
            *(float4*)&Vs[r][d4] = *(const float4*)(vb + (size_t)(k0 + r) * HD + d4);
        }
        __syncthreads();
        if (valid) {
            for (int kk = 0; kk < TK; kk++) {
                float s = 0.f;
                #pragma unroll
                for (int d = 0; d < HD; d += 4) {
                    float4 kv = *(const float4*)&Ks[kk][d];
                    s += qr[d]*kv.x + qr[d+1]*kv.y + qr[d+2]*kv.z + qr[d+3]*kv.w;
                }
                s *= SCALE;
                if (s > mval) {
                    const float corr = __expf(mval - s);
                    lsum = lsum * corr + 1.f;
                    mval = s;
                    #pragma unroll
                    for (int d = 0; d < HD; d += 4) {
                        float4 vv = *(const float4*)&Vs[kk][d];
                        acc[d]   = acc[d]  *corr + vv.x;
                        acc[d+1] = acc[d+1]*corr + vv.y;
                        acc[d+2] = acc[d+2]*corr + vv.z;
                        acc[d+3] = acc[d+3]*corr + vv.w;
                    }
                } else {
                    const float p = __expf(s - mval);
                    lsum += p;
                    #pragma unroll
                    for (int d = 0; d < HD; d += 4) {
                        float4 vv = *(const float4*)&Vs[kk][d];
                        acc[d]   += p * vv.x;
                        acc[d+1] += p * vv.y;
                        acc[d+2] += p * vv.z;
                        acc[d+3] += p * vv.w;
                    }
                }
            }
        }
        __syncthreads();
    }

    if (valid) {
        const float inv = 1.f / lsum;
        const int b = bh / HEADS, head = bh - b * HEADS;
        float* od = o_out + ((size_t)b * NP + qi) * C + head * HD;
        #pragma unroll
        for (int d = 0; d < HD; d += 4) {
            float4 t;
            t.x = acc[d]*inv; t.y = acc[d+1]*inv; t.z = acc[d+2]*inv; t.w = acc[d+3]*inv;
            *(float4*)(od + d) = t;
        }
    }
}

// =====================================================================
// Kernel 3: depthwise ConvTranspose2d (sr=2) upsample + bias + LayerNorm.
// One block (128 thr) per output pixel row (b, hi, wi); 3 channels/thread.
// =====================================================================
__global__ __launch_bounds__(128) void up_ln_kernel(
    const float* __restrict__ lp_w, const float* __restrict__ lp_b,
    const float* __restrict__ ln_w, const float* __restrict__ ln_b)
{
    const int pix = blockIdx.x;                  // b*3136 + hi*56 + wi
    const int b   = pix / NPIX;
    const int p2  = pix - b * NPIX;
    const int hi  = p2 / WW;
    const int wi  = p2 - hi * WW;
    const int hh = hi >> 1, pp = hi & 1;
    const int ww = wi >> 1, qq = wi & 1;
    const float* orow = g_o + ((size_t)b * NP + hh * PW + ww) * C;

    const int tid = threadIdx.x;
    float t[3];
    float s = 0.f, s2 = 0.f;
    #pragma unroll
    for (int r = 0; r < 3; r++) {
        const int c = tid + r * 128;
        const float val = orow[c] * lp_w[c*4 + pp*2 + qq] + lp_b[c];
        t[r] = val;
        s += val; s2 += val * val;
    }

    // block reduction (4 warps)
    __shared__ float rs[4], rs2[4];
    #pragma unroll
    for (int off = 16; off > 0; off >>= 1) {
        s  += __shfl_down_sync(0xffffffffu, s,  off);
        s2 += __shfl_down_sync(0xffffffffu, s2, off);
    }
    if ((tid & 31) == 0) { rs[tid >> 5] = s; rs2[tid >> 5] = s2; }
    __syncthreads();
    const float S  = rs[0] + rs[1] + rs[2] + rs[3];
    const float S2 = rs2[0] + rs2[1] + rs2[2] + rs2[3];
    const float mean = S * (1.f / C);
    const float var  = S2 * (1.f / C) - mean * mean;
    const float inv  = rsqrtf(var + EPS);

    float* yrow = g_y + (size_t)pix * C;
    #pragma unroll
    for (int r = 0; r < 3; r++) {
        const int c = tid + r * 128;
        yrow[c] = (t[r] - mean) * inv * ln_w[c] + ln_b[c];
    }
}

// =====================================================================
// Kernel 4: proj GEMM  out[m, j] = sum_c y[m, c] * proj_w[j, c] + proj_b[j]
// M = 50176, N = 384, K = 384.  Same 64x64x16 tiling.
// =====================================================================
__global__ __launch_bounds__(256) void proj_gemm_kernel(
    const float* __restrict__ w, const float* __restrict__ bias,
    float* __restrict__ out)
{
    __shared__ float As[BK][BM];
    __shared__ float Bs[BK][BN];

    const int tile_n = blockIdx.x * BN;
    const int tile_m = blockIdx.y * BM;
    const int tid = threadIdx.x;
    const int tx = tid & 15;
    const int ty = tid >> 4;

    const int lrow = tid >> 2;
    const int lk   = (tid & 3) * 4;

    const float* a_src = g_y + (size_t)(tile_m + lrow) * C;
    const float* b_src = w   + (size_t)(tile_n + lrow) * C;

    float acc[4][4] = {};

    for (int k0 = 0; k0 < C; k0 += BK) {
        float4 av = *(const float4*)(a_src + k0 + lk);
        float4 bv = *(const float4*)(b_src + k0 + lk);
        As[lk+0][lrow] = av.x; As[lk+1][lrow] = av.y;
        As[lk+2][lrow] = av.z; As[lk+3][lrow] = av.w;
        Bs[lk+0][lrow] = bv.x; Bs[lk+1][lrow] = bv.y;
        Bs[lk+2][lrow] = bv.z; Bs[lk+3][lrow] = bv.w;
        __syncthreads();
        #pragma unroll
        for (int kk = 0; kk < BK; kk++) {
            float a[4], bb[4];
            #pragma unroll
            for (int t = 0; t < 4; t++) a[t]  = As[kk][ty*4 + t];
            #pragma unroll
            for (int t = 0; t < 4; t++) bb[t] = Bs[kk][tx*4 + t];
            #pragma unroll
            for (int ii = 0; ii < 4; ii++)
                #pragma unroll
                for (int jj = 0; jj < 4; jj++)
                    acc[ii][jj] += a[ii] * bb[jj];
        }
        __syncthreads();
    }

    #pragma unroll
    for (int ii = 0; ii < 4; ii++) {
        const int gm = tile_m + ty*4 + ii;
        #pragma unroll
        for (int jj = 0; jj < 4; jj++) {
            const int gj = tile_n + tx*4 + jj;
            out[(size_t)gm * C + gj] = acc[ii][jj] + bias[gj];
        }
    }
}

// =====================================================================
// launcher
// =====================================================================
extern "C" void kernel_launch(void* const* d_in, const int* in_sizes, int n_in,
                              void* d_out, int out_size)
{
    const float* x      = (const float*)d_in[0];
    const float* qkv_w  = (const float*)d_in[1];
    const float* qkv_b  = (const float*)d_in[2];
    const float* proj_w = (const float*)d_in[3];
    const float* proj_b = (const float*)d_in[4];
    const float* lp_w   = (const float*)d_in[5];
    const float* lp_b   = (const float*)d_in[6];
    const float* ln_w   = (const float*)d_in[7];
    const float* ln_b   = (const float*)d_in[8];
    float* out = (float*)d_out;

    // device-global scratch pointers resolved inside kernels; get g_o address
    // via cudaGetSymbolAddress is not needed (kernels reference symbols),
    // but attn writes through a pointer parameter:
    float* o_ptr = nullptr;
    cudaGetSymbolAddress((void**)&o_ptr, g_o);

    // 1) QKV gemm: M=12544 (196 tiles), N=1152 (18 tiles)
    {
        dim3 grid(1152 / BN, (BATCH * NP) / BM);
        qkv_gemm_kernel<<<grid, 256>>>(x, qkv_w, qkv_b);
    }
    // 2) attention: 7 q-blocks x 128 (b,h)
    {
        dim3 grid((NP + 127) / 128, BH);
        attn_kernel<<<grid, 128>>>(o_ptr);
    }
    // 3) upsample + LN: one block per output pixel
    {
        up_ln_kernel<<<BATCH * NPIX, 128>>>(lp_w, lp_b, ln_w, ln_b);
    }
    // 4) proj gemm: M=50176 (784 tiles), N=384 (6 tiles)
    {
        dim3 grid(C / BN, (BATCH * NPIX) / BM);
        proj_gemm_kernel<<<grid, 256>>>(proj_w, proj_b, out);
    }
}

// round 2
// speedup vs baseline: 2.2100x; 2.2100x over previous
#include <cuda_runtime.h>
#include <cstdint>

// ---------------- problem constants ----------------
#define BATCH   16
#define HH      56
#define WW      56
#define NPIX    (HH*WW)        // 3136
#define C       384
#define HEADS   8
#define HD      48
#define SRR     2
#define PH      (HH/SRR)       // 28
#define PW      (WW/SRR)       // 28
#define NP      (PH*PW)        // 784
#define BH      (BATCH*HEADS)  // 128
#define SCALE   0.14433756729740643f  // 48^-0.5
#define EPS     1e-5f

// ---------------- scratch ----------------
__device__ float g_q[(size_t)BH * NP * HD];
__device__ float g_k[(size_t)BH * NP * HD];
__device__ float g_v[(size_t)BH * NP * HD];
__device__ float g_o[(size_t)BATCH * NP * C];
__device__ float g_y[(size_t)BATCH * NPIX * C];

// ---------------- tf32 helpers ----------------
__device__ __forceinline__ uint32_t f2tf(float f) {
    uint32_t u;
    asm("cvt.rna.tf32.f32 %0, %1;" : "=r"(u) : "f"(f));
    return u;
}

__device__ __forceinline__ void mma_tf32(float* d, const uint32_t* a, const uint32_t* b) {
    asm volatile(
        "mma.sync.aligned.m16n8k8.row.col.f32.tf32.tf32.f32 "
        "{%0,%1,%2,%3}, {%4,%5,%6,%7}, {%8,%9}, {%0,%1,%2,%3};\n"
        : "+f"(d[0]), "+f"(d[1]), "+f"(d[2]), "+f"(d[3])
        : "r"(a[0]), "r"(a[1]), "r"(a[2]), "r"(a[3]),
          "r"(b[0]), "r"(b[1]));
}

// ====================================================================
// tf32 GEMM core: block tile 128(m) x 128(n), BK=32, 256 threads.
// 8 warps: warp_m = wid&3 (32 rows), warp_n = wid>>2 (64 cols).
// Each warp: 2 m-subtiles x 8 n-subtiles of m16n8k8.
// A: row-major M x K.  B: row-major N x K (= col-major K x N for mma).
// ====================================================================
#define GBK 32
#define GPAD 33

// =====================================================================
// Kernel 1: QKV GEMM (fused strided subsample of x on the A side).
// M=12544, N=1152, K=384.  Epilogue scatters into g_q/g_k/g_v + bias.
// =====================================================================
__global__ __launch_bounds__(256) void qkv_gemm_tf32(
    const float* __restrict__ x, const float* __restrict__ w,
    const float* __restrict__ bias)
{
    __shared__ uint32_t As[128][GPAD];
    __shared__ uint32_t Bs[128][GPAD];

    const int tile_m = blockIdx.y * 128;
    const int tile_n = blockIdx.x * 128;
    const int tid  = threadIdx.x;
    const int wid  = tid >> 5;
    const int lane = tid & 31;
    const int gid  = lane >> 2;      // 0..7
    const int t4   = lane & 3;       // 0..3
    const int warp_m = (wid & 3) * 32;
    const int warp_n = (wid >> 2) * 64;

    // precompute the 4 (row, k4) slots this thread fills each k-step
    const float* aptr[4];
    const float* bptr[4];
    int arow[4], ak4[4];
    #pragma unroll
    for (int r = 0; r < 4; r++) {
        const int idx = tid + r * 256;       // 0..1023
        const int row = idx >> 3;            // 0..127
        const int k4  = (idx & 7) * 4;
        arow[r] = row; ak4[r] = k4;
        const int m  = tile_m + row;
        const int b  = m / NP;
        const int i  = m - b * NP;
        const int hi = (i / PW) * SRR;
        const int wi = (i - (i / PW) * PW) * SRR;
        aptr[r] = x + ((size_t)b * NPIX + hi * WW + wi) * C + k4;
        bptr[r] = w + (size_t)(tile_n + row) * C + k4;
    }

    float acc[2][8][4] = {};

    for (int k0 = 0; k0 < C; k0 += GBK) {
        #pragma unroll
        for (int r = 0; r < 4; r++) {
            const float4 av = *(const float4*)(aptr[r] + k0);
            const float4 bv = *(const float4*)(bptr[r] + k0);
            uint32_t* ad = &As[arow[r]][ak4[r]];
            ad[0] = f2tf(av.x); ad[1] = f2tf(av.y); ad[2] = f2tf(av.z); ad[3] = f2tf(av.w);
            uint32_t* bd = &Bs[arow[r]][ak4[r]];
            bd[0] = f2tf(bv.x); bd[1] = f2tf(bv.y); bd[2] = f2tf(bv.z); bd[3] = f2tf(bv.w);
        }
        __syncthreads();
        #pragma unroll
        for (int ks = 0; ks < GBK; ks += 8) {
            uint32_t af[2][4], bf[8][2];
            #pragma unroll
            for (int i = 0; i < 2; i++) {
                const int r0 = warp_m + i * 16 + gid;
                af[i][0] = As[r0][ks + t4];
                af[i][1] = As[r0 + 8][ks + t4];
                af[i][2] = As[r0][ks + t4 + 4];
                af[i][3] = As[r0 + 8][ks + t4 + 4];
            }
            #pragma unroll
            for (int j = 0; j < 8; j++) {
                const int cc = warp_n + j * 8 + gid;
                bf[j][0] = Bs[cc][ks + t4];
                bf[j][1] = Bs[cc][ks + t4 + 4];
            }
            #pragma unroll
            for (int i = 0; i < 2; i++)
                #pragma unroll
                for (int j = 0; j < 8; j++)
                    mma_tf32(acc[i][j], af[i], bf[j]);
        }
        __syncthreads();
    }

    // epilogue: bias + scatter to q/k/v  [bh][i][d]
    #pragma unroll
    for (int i = 0; i < 2; i++) {
        #pragma unroll
        for (int half = 0; half < 2; half++) {
            const int gm = tile_m + warp_m + i * 16 + gid + half * 8;
            const int ob = gm / NP;
            const int oi = gm - ob * NP;
            #pragma unroll
            for (int j = 0; j < 8; j++) {
                #pragma unroll
                for (int e = 0; e < 2; e++) {
                    const int gj = tile_n + warp_n + j * 8 + 2 * t4 + e;
                    const float val = acc[i][j][half * 2 + e] + bias[gj];
                    const int which = gj / C;
                    const int c2    = gj - which * C;
                    const int head  = c2 / HD;
                    const int d     = c2 - head * HD;
                    const size_t idx = ((size_t)(ob * HEADS + head) * NP + oi) * HD + d;
                    if (which == 0)      g_q[idx] = val;
                    else if (which == 1) g_k[idx] = val;
                    else                 g_v[idx] = val;
                }
            }
        }
    }
}

// =====================================================================
// Kernel 4: proj GEMM, M=50176, N=384, K=384 (A = g_y).
// =====================================================================
__global__ __launch_bounds__(256) void proj_gemm_tf32(
    const float* __restrict__ w, const float* __restrict__ bias,
    float* __restrict__ out)
{
    __shared__ uint32_t As[128][GPAD];
    __shared__ uint32_t Bs[128][GPAD];

    const int tile_m = blockIdx.y * 128;
    const int tile_n = blockIdx.x * 128;
    const int tid  = threadIdx.x;
    const int wid  = tid >> 5;
    const int lane = tid & 31;
    const int gid  = lane >> 2;
    const int t4   = lane & 3;
    const int warp_m = (wid & 3) * 32;
    const int warp_n = (wid >> 2) * 64;

    const float* aptr[4];
    const float* bptr[4];
    int arow[4], ak4[4];
    #pragma unroll
    for (int r = 0; r < 4; r++) {
        const int idx = tid + r * 256;
        const int row = idx >> 3;
        const int k4  = (idx & 7) * 4;
        arow[r] = row; ak4[r] = k4;
        aptr[r] = g_y + (size_t)(tile_m + row) * C + k4;
        bptr[r] = w   + (size_t)(tile_n + row) * C + k4;
    }

    float acc[2][8][4] = {};

    for (int k0 = 0; k0 < C; k0 += GBK) {
        #pragma unroll
        for (int r = 0; r < 4; r++) {
            const float4 av = *(const float4*)(aptr[r] + k0);
            const float4 bv = *(const float4*)(bptr[r] + k0);
            uint32_t* ad = &As[arow[r]][ak4[r]];
            ad[0] = f2tf(av.x); ad[1] = f2tf(av.y); ad[2] = f2tf(av.z); ad[3] = f2tf(av.w);
            uint32_t* bd = &Bs[arow[r]][ak4[r]];
            bd[0] = f2tf(bv.x); bd[1] = f2tf(bv.y); bd[2] = f2tf(bv.z); bd[3] = f2tf(bv.w);
        }
        __syncthreads();
        #pragma unroll
        for (int ks = 0; ks < GBK; ks += 8) {
            uint32_t af[2][4], bf[8][2];
            #pragma unroll
            for (int i = 0; i < 2; i++) {
                const int r0 = warp_m + i * 16 + gid;
                af[i][0] = As[r0][ks + t4];
                af[i][1] = As[r0 + 8][ks + t4];
                af[i][2] = As[r0][ks + t4 + 4];
                af[i][3] = As[r0 + 8][ks + t4 + 4];
            }
            #pragma unroll
            for (int j = 0; j < 8; j++) {
                const int cc = warp_n + j * 8 + gid;
                bf[j][0] = Bs[cc][ks + t4];
                bf[j][1] = Bs[cc][ks + t4 + 4];
            }
            #pragma unroll
            for (int i = 0; i < 2; i++)
                #pragma unroll
                for (int j = 0; j < 8; j++)
                    mma_tf32(acc[i][j], af[i], bf[j]);
        }
        __syncthreads();
    }

    // epilogue: bias + store (cols 2*t4, 2*t4+1 contiguous -> float2)
    #pragma unroll
    for (int i = 0; i < 2; i++) {
        #pragma unroll
        for (int half = 0; half < 2; half++) {
            const int gm = tile_m + warp_m + i * 16 + gid + half * 8;
            #pragma unroll
            for (int j = 0; j < 8; j++) {
                const int gj = tile_n + warp_n + j * 8 + 2 * t4;
                float2 v;
                v.x = acc[i][j][half * 2 + 0] + bias[gj];
                v.y = acc[i][j][half * 2 + 1] + bias[gj + 1];
                *(float2*)(out + (size_t)gm * C + gj) = v;
            }
        }
    }
}

// =====================================================================
// Kernel 2: flash attention per (b,h). One q-row per thread, K/V tiles
// staged in smem (broadcast LDS), online softmax.
// =====================================================================
#define TK 112
__global__ __launch_bounds__(128) void attn_kernel(float* __restrict__ o_out)
{
    __shared__ float Ks[TK][HD];
    __shared__ float Vs[TK][HD];

    const int bh = blockIdx.y;
    const int qi = blockIdx.x * 128 + threadIdx.x;
    const bool valid = (qi < NP);

    const float* kb = g_k + (size_t)bh * NP * HD;
    const float* vb = g_v + (size_t)bh * NP * HD;

    float qr[HD];
    if (valid) {
        const float* qp = g_q + ((size_t)bh * NP + qi) * HD;
        #pragma unroll
        for (int d = 0; d < HD; d += 4) {
            float4 t = *(const float4*)(qp + d);
            qr[d] = t.x; qr[d+1] = t.y; qr[d+2] = t.z; qr[d+3] = t.w;
        }
    }

    float mval = -1e30f, lsum = 0.f;
    float acc[HD] = {};

    for (int k0 = 0; k0 < NP; k0 += TK) {
        for (int idx = threadIdx.x; idx < TK * (HD/4); idx += 128) {
            const int r  = idx / (HD/4);
            const int d4 = (idx - r * (HD/4)) * 4;
            *(float4*)&Ks[r][d4] = *(const float4*)(kb + (size_t)(k0 + r) * HD + d4);
            *(float4*)&Vs[r][d4] = *(const float4*)(vb + (size_t)(k0 + r) * HD + d4);
        }
        __syncthreads();
        if (valid) {
            for (int kk = 0; kk < TK; kk++) {
                float s = 0.f;
                #pragma unroll
                for (int d = 0; d < HD; d += 4) {
                    float4 kv = *(const float4*)&Ks[kk][d];
                    s += qr[d]*kv.x + qr[d+1]*kv.y + qr[d+2]*kv.z + qr[d+3]*kv.w;
                }
                s *= SCALE;
                if (s > mval) {
                    const float corr = __expf(mval - s);
                    lsum = lsum * corr + 1.f;
                    mval = s;
                    #pragma unroll
                    for (int d = 0; d < HD; d += 4) {
                        float4 vv = *(const float4*)&Vs[kk][d];
                        acc[d]   = acc[d]  *corr + vv.x;
                        acc[d+1] = acc[d+1]*corr + vv.y;
                        acc[d+2] = acc[d+2]*corr + vv.z;
                        acc[d+3] = acc[d+3]*corr + vv.w;
                    }
                } else {
                    const float p = __expf(s - mval);
                    lsum += p;
                    #pragma unroll
                    for (int d = 0; d < HD; d += 4) {
                        float4 vv = *(const float4*)&Vs[kk][d];
                        acc[d]   += p * vv.x;
                        acc[d+1] += p * vv.y;
                        acc[d+2] += p * vv.z;
                        acc[d+3] += p * vv.w;
                    }
                }
            }
        }
        __syncthreads();
    }

    if (valid) {
        const float inv = 1.f / lsum;
        const int b = bh / HEADS, head = bh - b * HEADS;
        float* od = o_out + ((size_t)b * NP + qi) * C + head * HD;
        #pragma unroll
        for (int d = 0; d < HD; d += 4) {
            float4 t;
            t.x = acc[d]*inv; t.y = acc[d+1]*inv; t.z = acc[d+2]*inv; t.w = acc[d+3]*inv;
            *(float4*)(od + d) = t;
        }
    }
}

// =====================================================================
// Kernel 3: depthwise ConvT upsample + bias + LayerNorm.
// =====================================================================
__global__ __launch_bounds__(128) void up_ln_kernel(
    const float* __restrict__ lp_w, const float* __restrict__ lp_b,
    const float* __restrict__ ln_w, const float* __restrict__ ln_b)
{
    const int pix = blockIdx.x;
    const int b   = pix / NPIX;
    const int p2  = pix - b * NPIX;
    const int hi  = p2 / WW;
    const int wi  = p2 - hi * WW;
    const int hh = hi >> 1, pp = hi & 1;
    const int ww = wi >> 1, qq = wi & 1;
    const float* orow = g_o + ((size_t)b * NP + hh * PW + ww) * C;

    const int tid = threadIdx.x;
    float t[3];
    float s = 0.f, s2 = 0.f;
    #pragma unroll
    for (int r = 0; r < 3; r++) {
        const int c = tid + r * 128;
        const float val = orow[c] * lp_w[c*4 + pp*2 + qq] + lp_b[c];
        t[r] = val;
        s += val; s2 += val * val;
    }

    __shared__ float rs[4], rs2[4];
    #pragma unroll
    for (int off = 16; off > 0; off >>= 1) {
        s  += __shfl_down_sync(0xffffffffu, s,  off);
        s2 += __shfl_down_sync(0xffffffffu, s2, off);
    }
    if ((tid & 31) == 0) { rs[tid >> 5] = s; rs2[tid >> 5] = s2; }
    __syncthreads();
    const float S  = rs[0] + rs[1] + rs[2] + rs[3];
    const float S2 = rs2[0] + rs2[1] + rs2[2] + rs2[3];
    const float mean = S * (1.f / C);
    const float var  = S2 * (1.f / C) - mean * mean;
    const float inv  = rsqrtf(var + EPS);

    float* yrow = g_y + (size_t)pix * C;
    #pragma unroll
    for (int r = 0; r < 3; r++) {
        const int c = tid + r * 128;
        yrow[c] = (t[r] - mean) * inv * ln_w[c] + ln_b[c];
    }
}

// =====================================================================
// launcher
// =====================================================================
extern "C" void kernel_launch(void* const* d_in, const int* in_sizes, int n_in,
                              void* d_out, int out_size)
{
    const float* x      = (const float*)d_in[0];
    const float* qkv_w  = (const float*)d_in[1];
    const float* qkv_b  = (const float*)d_in[2];
    const float* proj_w = (const float*)d_in[3];
    const float* proj_b = (const float*)d_in[4];
    const float* lp_w   = (const float*)d_in[5];
    const float* lp_b   = (const float*)d_in[6];
    const float* ln_w   = (const float*)d_in[7];
    const float* ln_b   = (const float*)d_in[8];
    float* out = (float*)d_out;

    float* o_ptr = nullptr;
    cudaGetSymbolAddress((void**)&o_ptr, g_o);

    // 1) QKV gemm: M=12544 (98 tiles), N=1152 (9 tiles)
    {
        dim3 grid(1152 / 128, (BATCH * NP) / 128);
        qkv_gemm_tf32<<<grid, 256>>>(x, qkv_w, qkv_b);
    }
    // 2) attention
    {
        dim3 grid((NP + 127) / 128, BH);
        attn_kernel<<<grid, 128>>>(o_ptr);
    }
    // 3) upsample + LN
    {
        up_ln_kernel<<<BATCH * NPIX, 128>>>(lp_w, lp_b, ln_w, ln_b);
    }
    // 4) proj gemm: M=50176 (392 tiles), N=384 (3 tiles)
    {
        dim3 grid(C / 128, (BATCH * NPIX) / 128);
        proj_gemm_tf32<<<grid, 256>>>(proj_w, proj_b, out);
    }
}

// round 3
// speedup vs baseline: 3.9634x; 1.7934x over previous
#include <cuda_runtime.h>
#include <cstdint>

// ---------------- problem constants ----------------
#define BATCH   16
#define HH      56
#define WW      56
#define NPIX    (HH*WW)        // 3136
#define C       384
#define HEADS   8
#define HD      48
#define SRR     2
#define PH      (HH/SRR)       // 28
#define PW      (WW/SRR)       // 28
#define NP      (PH*PW)        // 784
#define BH      (BATCH*HEADS)  // 128
#define SCALE   0.14433756729740643f  // 48^-0.5
#define EPS     1e-5f

// ---------------- scratch ----------------
__device__ float g_q[(size_t)BH * NP * HD];
__device__ float g_k[(size_t)BH * NP * HD];
__device__ float g_v[(size_t)BH * NP * HD];
__device__ float g_o[(size_t)BATCH * NP * C];
__device__ float g_y[(size_t)BATCH * NPIX * C];

// ---------------- tf32 helpers ----------------
__device__ __forceinline__ uint32_t f2tf(float f) {
    uint32_t u;
    asm("cvt.rna.tf32.f32 %0, %1;" : "=r"(u) : "f"(f));
    return u;
}

__device__ __forceinline__ void mma_tf32(float* d, const uint32_t* a, const uint32_t* b) {
    asm volatile(
        "mma.sync.aligned.m16n8k8.row.col.f32.tf32.tf32.f32 "
        "{%0,%1,%2,%3}, {%4,%5,%6,%7}, {%8,%9}, {%0,%1,%2,%3};\n"
        : "+f"(d[0]), "+f"(d[1]), "+f"(d[2]), "+f"(d[3])
        : "r"(a[0]), "r"(a[1]), "r"(a[2]), "r"(a[3]),
          "r"(b[0]), "r"(b[1]));
}

#define GBK 32
#define GPAD 33

// =====================================================================
// Kernel 1: QKV GEMM (fused strided subsample of x on the A side).
// M=12544, N=1152, K=384.  Epilogue scatters into g_q/g_k/g_v + bias.
// =====================================================================
__global__ __launch_bounds__(256) void qkv_gemm_tf32(
    const float* __restrict__ x, const float* __restrict__ w,
    const float* __restrict__ bias)
{
    __shared__ uint32_t As[128][GPAD];
    __shared__ uint32_t Bs[128][GPAD];

    const int tile_m = blockIdx.y * 128;
    const int tile_n = blockIdx.x * 128;
    const int tid  = threadIdx.x;
    const int wid  = tid >> 5;
    const int lane = tid & 31;
    const int gid  = lane >> 2;
    const int t4   = lane & 3;
    const int warp_m = (wid & 3) * 32;
    const int warp_n = (wid >> 2) * 64;

    const float* aptr[4];
    const float* bptr[4];
    int arow[4], ak4[4];
    #pragma unroll
    for (int r = 0; r < 4; r++) {
        const int idx = tid + r * 256;
        const int row = idx >> 3;
        const int k4  = (idx & 7) * 4;
        arow[r] = row; ak4[r] = k4;
        const int m  = tile_m + row;
        const int b  = m / NP;
        const int i  = m - b * NP;
        const int hi = (i / PW) * SRR;
        const int wi = (i - (i / PW) * PW) * SRR;
        aptr[r] = x + ((size_t)b * NPIX + hi * WW + wi) * C + k4;
        bptr[r] = w + (size_t)(tile_n + row) * C + k4;
    }

    float acc[2][8][4] = {};

    for (int k0 = 0; k0 < C; k0 += GBK) {
        #pragma unroll
        for (int r = 0; r < 4; r++) {
            const float4 av = *(const float4*)(aptr[r] + k0);
            const float4 bv = *(const float4*)(bptr[r] + k0);
            uint32_t* ad = &As[arow[r]][ak4[r]];
            ad[0] = f2tf(av.x); ad[1] = f2tf(av.y); ad[2] = f2tf(av.z); ad[3] = f2tf(av.w);
            uint32_t* bd = &Bs[arow[r]][ak4[r]];
            bd[0] = f2tf(bv.x); bd[1] = f2tf(bv.y); bd[2] = f2tf(bv.z); bd[3] = f2tf(bv.w);
        }
        __syncthreads();
        #pragma unroll
        for (int ks = 0; ks < GBK; ks += 8) {
            uint32_t af[2][4], bf[8][2];
            #pragma unroll
            for (int i = 0; i < 2; i++) {
                const int r0 = warp_m + i * 16 + gid;
                af[i][0] = As[r0][ks + t4];
                af[i][1] = As[r0 + 8][ks + t4];
                af[i][2] = As[r0][ks + t4 + 4];
                af[i][3] = As[r0 + 8][ks + t4 + 4];
            }
            #pragma unroll
            for (int j = 0; j < 8; j++) {
                const int cc = warp_n + j * 8 + gid;
                bf[j][0] = Bs[cc][ks + t4];
                bf[j][1] = Bs[cc][ks + t4 + 4];
            }
            #pragma unroll
            for (int i = 0; i < 2; i++)
                #pragma unroll
                for (int j = 0; j < 8; j++)
                    mma_tf32(acc[i][j], af[i], bf[j]);
        }
        __syncthreads();
    }

    #pragma unroll
    for (int i = 0; i < 2; i++) {
        #pragma unroll
        for (int half = 0; half < 2; half++) {
            const int gm = tile_m + warp_m + i * 16 + gid + half * 8;
            const int ob = gm / NP;
            const int oi = gm - ob * NP;
            #pragma unroll
            for (int j = 0; j < 8; j++) {
                #pragma unroll
                for (int e = 0; e < 2; e++) {
                    const int gj = tile_n + warp_n + j * 8 + 2 * t4 + e;
                    const float val = acc[i][j][half * 2 + e] + bias[gj];
                    const int which = gj / C;
                    const int c2    = gj - which * C;
                    const int head  = c2 / HD;
                    const int d     = c2 - head * HD;
                    const size_t idx = ((size_t)(ob * HEADS + head) * NP + oi) * HD + d;
                    if (which == 0)      g_q[idx] = val;
                    else if (which == 1) g_k[idx] = val;
                    else                 g_v[idx] = val;
                }
            }
        }
    }
}

// =====================================================================
// Kernel 2: flash attention, tf32 mma.
// CTA = 112 q-rows (7 warps x 16), kv tiles of 56 keys.
// grid = (NP/112 = 7, BH = 128), 224 threads.
// =====================================================================
#define QB 112
#define KB 56
#define ATHREADS 224
#define KSTRIDE 52   // 52 mod 32 = 20 -> conflict-free B-frag reads
#define VSTRIDE 60   // 60 mod 32 = 28 -> conflict-free B-frag reads

__global__ __launch_bounds__(ATHREADS, 2) void attn_mma(float* __restrict__ o_out)
{
    __shared__ uint32_t Ks[KB][KSTRIDE];   // [key][d]  tf32 bits
    __shared__ uint32_t Vst[HD][VSTRIDE];  // [d][key]  tf32 bits (V transposed)

    const int bh = blockIdx.y;
    const int qbase = blockIdx.x * QB;
    const int tid  = threadIdx.x;
    const int w    = tid >> 5;
    const int lane = tid & 31;
    const int gid  = lane >> 2;
    const int t4   = lane & 3;

    const float* kbp = g_k + (size_t)bh * NP * HD;
    const float* vbp = g_v + (size_t)bh * NP * HD;

    // Q fragments (pre-scaled by softmax scale), rows q0=qbase+w*16+gid, q1=q0+8
    uint32_t qa[6][4];
    {
        const float* q0 = g_q + ((size_t)bh * NP + qbase + w * 16 + gid) * HD;
        const float* q1 = q0 + 8 * HD;
        #pragma unroll
        for (int ks = 0; ks < 6; ks++) {
            qa[ks][0] = f2tf(SCALE * q0[ks * 8 + t4]);
            qa[ks][1] = f2tf(SCALE * q1[ks * 8 + t4]);
            qa[ks][2] = f2tf(SCALE * q0[ks * 8 + t4 + 4]);
            qa[ks][3] = f2tf(SCALE * q1[ks * 8 + t4 + 4]);
        }
    }

    float m0 = -1e30f, m1 = -1e30f, l0 = 0.f, l1 = 0.f;
    float oacc[6][4] = {};

    for (int kt = 0; kt < NP / KB; kt++) {
        __syncthreads();
        // cooperative K/V tile load (K direct, V transposed), convert to tf32
        for (int idx = tid; idx < KB * (HD / 4); idx += ATHREADS) {
            const int key = idx / (HD / 4);
            const int d4  = (idx - key * (HD / 4)) * 4;
            const size_t goff = (size_t)(kt * KB + key) * HD + d4;
            float4 kv = *(const float4*)(kbp + goff);
            Ks[key][d4 + 0] = f2tf(kv.x); Ks[key][d4 + 1] = f2tf(kv.y);
            Ks[key][d4 + 2] = f2tf(kv.z); Ks[key][d4 + 3] = f2tf(kv.w);
            float4 vv = *(const float4*)(vbp + goff);
            Vst[d4 + 0][key] = f2tf(vv.x); Vst[d4 + 1][key] = f2tf(vv.y);
            Vst[d4 + 2][key] = f2tf(vv.z); Vst[d4 + 3][key] = f2tf(vv.w);
        }
        __syncthreads();

        // S = Qscaled @ K^T : 7 n-tiles (8 keys each) x 6 k-steps
        float s[7][4] = {};
        #pragma unroll
        for (int j = 0; j < 7; j++) {
            #pragma unroll
            for (int ks = 0; ks < 6; ks++) {
                uint32_t bfr[2];
                bfr[0] = Ks[j * 8 + gid][ks * 8 + t4];
                bfr[1] = Ks[j * 8 + gid][ks * 8 + t4 + 4];
                mma_tf32(s[j], qa[ks], bfr);
            }
        }

        // online softmax (rows r0 = gid, r1 = gid+8)
        float mx0 = -1e30f, mx1 = -1e30f;
        #pragma unroll
        for (int j = 0; j < 7; j++) {
            mx0 = fmaxf(mx0, fmaxf(s[j][0], s[j][1]));
            mx1 = fmaxf(mx1, fmaxf(s[j][2], s[j][3]));
        }
        mx0 = fmaxf(mx0, __shfl_xor_sync(0xffffffffu, mx0, 1));
        mx0 = fmaxf(mx0, __shfl_xor_sync(0xffffffffu, mx0, 2));
        mx1 = fmaxf(mx1, __shfl_xor_sync(0xffffffffu, mx1, 1));
        mx1 = fmaxf(mx1, __shfl_xor_sync(0xffffffffu, mx1, 2));
        const float nm0 = fmaxf(m0, mx0);
        const float nm1 = fmaxf(m1, mx1);
        const float c0 = __expf(m0 - nm0);
        const float c1 = __expf(m1 - nm1);
        m0 = nm0; m1 = nm1;

        float ps0 = 0.f, ps1 = 0.f;
        #pragma unroll
        for (int j = 0; j < 7; j++) {
            s[j][0] = __expf(s[j][0] - nm0); ps0 += s[j][0];
            s[j][1] = __expf(s[j][1] - nm0); ps0 += s[j][1];
            s[j][2] = __expf(s[j][2] - nm1); ps1 += s[j][2];
            s[j][3] = __expf(s[j][3] - nm1); ps1 += s[j][3];
        }
        ps0 += __shfl_xor_sync(0xffffffffu, ps0, 1);
        ps0 += __shfl_xor_sync(0xffffffffu, ps0, 2);
        ps1 += __shfl_xor_sync(0xffffffffu, ps1, 1);
        ps1 += __shfl_xor_sync(0xffffffffu, ps1, 2);
        l0 = l0 * c0 + ps0;
        l1 = l1 * c1 + ps1;

        #pragma unroll
        for (int n = 0; n < 6; n++) {
            oacc[n][0] *= c0; oacc[n][1] *= c0;
            oacc[n][2] *= c1; oacc[n][3] *= c1;
        }

        // O += P @ V : convert each 16x8 P c-frag to A-frag via shuffles
        const int srcl = (lane & ~3) | (t4 >> 1);
        const bool odd = (t4 & 1);
        #pragma unroll
        for (int j = 0; j < 7; j++) {
            float v00 = __shfl_sync(0xffffffffu, s[j][0], srcl);
            float v01 = __shfl_sync(0xffffffffu, s[j][1], srcl);
            float v20 = __shfl_sync(0xffffffffu, s[j][2], srcl);
            float v21 = __shfl_sync(0xffffffffu, s[j][3], srcl);
            float v40 = __shfl_sync(0xffffffffu, s[j][0], srcl + 2);
            float v41 = __shfl_sync(0xffffffffu, s[j][1], srcl + 2);
            float v60 = __shfl_sync(0xffffffffu, s[j][2], srcl + 2);
            float v61 = __shfl_sync(0xffffffffu, s[j][3], srcl + 2);
            uint32_t a[4];
            a[0] = f2tf(odd ? v01 : v00);  // P[gid][t4]
            a[1] = f2tf(odd ? v21 : v20);  // P[gid+8][t4]
            a[2] = f2tf(odd ? v41 : v40);  // P[gid][t4+4]
            a[3] = f2tf(odd ? v61 : v60);  // P[gid+8][t4+4]
            #pragma unroll
            for (int n = 0; n < 6; n++) {
                uint32_t bfr[2];
                bfr[0] = Vst[n * 8 + gid][j * 8 + t4];
                bfr[1] = Vst[n * 8 + gid][j * 8 + t4 + 4];
                mma_tf32(oacc[n], a, bfr);
            }
        }
    }

    // write O / l, scatter to [b][q][head*48 + d]
    const int b = bh >> 3, head = bh & 7;
    const int q0r = qbase + w * 16 + gid;
    const float inv0 = 1.f / l0;
    const float inv1 = 1.f / l1;
    float* od0 = o_out + ((size_t)b * NP + q0r) * C + head * HD;
    float* od1 = od0 + (size_t)8 * C;
    #pragma unroll
    for (int n = 0; n < 6; n++) {
        const int col = n * 8 + 2 * t4;
        float2 r0; r0.x = oacc[n][0] * inv0; r0.y = oacc[n][1] * inv0;
        float2 r1; r1.x = oacc[n][2] * inv1; r1.y = oacc[n][3] * inv1;
        *(float2*)(od0 + col) = r0;
        *(float2*)(od1 + col) = r1;
    }
}

// =====================================================================
// Kernel 3: depthwise ConvT upsample + bias + LayerNorm.
// =====================================================================
__global__ __launch_bounds__(128) void up_ln_kernel(
    const float* __restrict__ lp_w, const float* __restrict__ lp_b,
    const float* __restrict__ ln_w, const float* __restrict__ ln_b)
{
    const int pix = blockIdx.x;
    const int b   = pix / NPIX;
    const int p2  = pix - b * NPIX;
    const int hi  = p2 / WW;
    const int wi  = p2 - hi * WW;
    const int hh = hi >> 1, pp = hi & 1;
    const int ww = wi >> 1, qq = wi & 1;
    const float* orow = g_o + ((size_t)b * NP + hh * PW + ww) * C;

    const int tid = threadIdx.x;
    float t[3];
    float s = 0.f, s2 = 0.f;
    #pragma unroll
    for (int r = 0; r < 3; r++) {
        const int c = tid + r * 128;
        const float val = orow[c] * lp_w[c*4 + pp*2 + qq] + lp_b[c];
        t[r] = val;
        s += val; s2 += val * val;
    }

    __shared__ float rs[4], rs2[4];
    #pragma unroll
    for (int off = 16; off > 0; off >>= 1) {
        s  += __shfl_down_sync(0xffffffffu, s,  off);
        s2 += __shfl_down_sync(0xffffffffu, s2, off);
    }
    if ((tid & 31) == 0) { rs[tid >> 5] = s; rs2[tid >> 5] = s2; }
    __syncthreads();
    const float S  = rs[0] + rs[1] + rs[2] + rs[3];
    const float S2 = rs2[0] + rs2[1] + rs2[2] + rs2[3];
    const float mean = S * (1.f / C);
    const float var  = S2 * (1.f / C) - mean * mean;
    const float inv  = rsqrtf(var + EPS);

    float* yrow = g_y + (size_t)pix * C;
    #pragma unroll
    for (int r = 0; r < 3; r++) {
        const int c = tid + r * 128;
        yrow[c] = (t[r] - mean) * inv * ln_w[c] + ln_b[c];
    }
}

// =====================================================================
// Kernel 4: proj GEMM, M=50176, N=384, K=384 (A = g_y).
// =====================================================================
__global__ __launch_bounds__(256) void proj_gemm_tf32(
    const float* __restrict__ w, const float* __restrict__ bias,
    float* __restrict__ out)
{
    __shared__ uint32_t As[128][GPAD];
    __shared__ uint32_t Bs[128][GPAD];

    const int tile_m = blockIdx.y * 128;
    const int tile_n = blockIdx.x * 128;
    const int tid  = threadIdx.x;
    const int wid  = tid >> 5;
    const int lane = tid & 31;
    const int gid  = lane >> 2;
    const int t4   = lane & 3;
    const int warp_m = (wid & 3) * 32;
    const int warp_n = (wid >> 2) * 64;

    const float* aptr[4];
    const float* bptr[4];
    int arow[4], ak4[4];
    #pragma unroll
    for (int r = 0; r < 4; r++) {
        const int idx = tid + r * 256;
        const int row = idx >> 3;
        const int k4  = (idx & 7) * 4;
        arow[r] = row; ak4[r] = k4;
        aptr[r] = g_y + (size_t)(tile_m + row) * C + k4;
        bptr[r] = w   + (size_t)(tile_n + row) * C + k4;
    }

    float acc[2][8][4] = {};

    for (int k0 = 0; k0 < C; k0 += GBK) {
        #pragma unroll
        for (int r = 0; r < 4; r++) {
            const float4 av = *(const float4*)(aptr[r] + k0);
            const float4 bv = *(const float4*)(bptr[r] + k0);
            uint32_t* ad = &As[arow[r]][ak4[r]];
            ad[0] = f2tf(av.x); ad[1] = f2tf(av.y); ad[2] = f2tf(av.z); ad[3] = f2tf(av.w);
            uint32_t* bd = &Bs[arow[r]][ak4[r]];
            bd[0] = f2tf(bv.x); bd[1] = f2tf(bv.y); bd[2] = f2tf(bv.z); bd[3] = f2tf(bv.w);
        }
        __syncthreads();
        #pragma unroll
        for (int ks = 0; ks < GBK; ks += 8) {
            uint32_t af[2][4], bf[8][2];
            #pragma unroll
            for (int i = 0; i < 2; i++) {
                const int r0 = warp_m + i * 16 + gid;
                af[i][0] = As[r0][ks + t4];
                af[i][1] = As[r0 + 8][ks + t4];
                af[i][2] = As[r0][ks + t4 + 4];
                af[i][3] = As[r0 + 8][ks + t4 + 4];
            }
            #pragma unroll
            for (int j = 0; j < 8; j++) {
                const int cc = warp_n + j * 8 + gid;
                bf[j][0] = Bs[cc][ks + t4];
                bf[j][1] = Bs[cc][ks + t4 + 4];
            }
            #pragma unroll
            for (int i = 0; i < 2; i++)
                #pragma unroll
                for (int j = 0; j < 8; j++)
                    mma_tf32(acc[i][j], af[i], bf[j]);
        }
        __syncthreads();
    }

    #pragma unroll
    for (int i = 0; i < 2; i++) {
        #pragma unroll
        for (int half = 0; half < 2; half++) {
            const int gm = tile_m + warp_m + i * 16 + gid + half * 8;
            #pragma unroll
            for (int j = 0; j < 8; j++) {
                const int gj = tile_n + warp_n + j * 8 + 2 * t4;
                float2 v;
                v.x = acc[i][j][half * 2 + 0] + bias[gj];
                v.y = acc[i][j][half * 2 + 1] + bias[gj + 1];
                *(float2*)(out + (size_t)gm * C + gj) = v;
            }
        }
    }
}

// =====================================================================
// launcher
// =====================================================================
extern "C" void kernel_launch(void* const* d_in, const int* in_sizes, int n_in,
                              void* d_out, int out_size)
{
    const float* x      = (const float*)d_in[0];
    const float* qkv_w  = (const float*)d_in[1];
    const float* qkv_b  = (const float*)d_in[2];
    const float* proj_w = (const float*)d_in[3];
    const float* proj_b = (const float*)d_in[4];
    const float* lp_w   = (const float*)d_in[5];
    const float* lp_b   = (const float*)d_in[6];
    const float* ln_w   = (const float*)d_in[7];
    const float* ln_b   = (const float*)d_in[8];
    float* out = (float*)d_out;

    float* o_ptr = nullptr;
    cudaGetSymbolAddress((void**)&o_ptr, g_o);

    // 1) QKV gemm
    {
        dim3 grid(1152 / 128, (BATCH * NP) / 128);
        qkv_gemm_tf32<<<grid, 256>>>(x, qkv_w, qkv_b);
    }
    // 2) attention (tf32 mma flash)
    {
        dim3 grid(NP / QB, BH);
        attn_mma<<<grid, ATHREADS>>>(o_ptr);
    }
    // 3) upsample + LN
    {
        up_ln_kernel<<<BATCH * NPIX, 128>>>(lp_w, lp_b, ln_w, ln_b);
    }
    // 4) proj gemm
    {
        dim3 grid(C / 128, (BATCH * NPIX) / 128);
        proj_gemm_tf32<<<grid, 256>>>(proj_w, proj_b, out);
    }
}

// round 4
// speedup vs baseline: 6.2182x; 1.5689x over previous
#include <cuda_runtime.h>
#include <cstdint>

// ---------------- problem constants ----------------
#define BATCH   16
#define HH      56
#define WW      56
#define NPIX    (HH*WW)        // 3136
#define C       384
#define HEADS   8
#define HD      48
#define SRR     2
#define PH      (HH/SRR)       // 28
#define PW      (WW/SRR)       // 28
#define NP      (PH*PW)        // 784
#define BH      (BATCH*HEADS)  // 128
#define SCALE   0.14433756729740643f  // 48^-0.5
#define EPS     1e-5f

// ---------------- scratch ----------------
__device__ float g_q[(size_t)BH * NP * HD];
__device__ float g_k[(size_t)BH * NP * HD];
__device__ float g_v[(size_t)BH * NP * HD];
__device__ float g_o[(size_t)BATCH * NP * C];
__device__ float g_y[(size_t)BATCH * NPIX * C];
__device__ float g_xp[(size_t)BATCH * NP * C];   // pooled, tf32-rounded x
__device__ float g_wq[(size_t)3 * C * C];        // tf32-rounded qkv_w
__device__ float g_wp[(size_t)C * C];            // tf32-rounded proj_w

// ---------------- tf32 helpers ----------------
__device__ __forceinline__ uint32_t f2tf(float f) {
    uint32_t u;
    asm("cvt.rna.tf32.f32 %0, %1;" : "=r"(u) : "f"(f));
    return u;
}
__device__ __forceinline__ float f2tf_f(float f) {
    return __uint_as_float(f2tf(f));
}

__device__ __forceinline__ void mma_tf32(float* d, const uint32_t* a, const uint32_t* b) {
    asm volatile(
        "mma.sync.aligned.m16n8k8.row.col.f32.tf32.tf32.f32 "
        "{%0,%1,%2,%3}, {%4,%5,%6,%7}, {%8,%9}, {%0,%1,%2,%3};\n"
        : "+f"(d[0]), "+f"(d[1]), "+f"(d[2]), "+f"(d[3])
        : "r"(a[0]), "r"(a[1]), "r"(a[2]), "r"(a[3]),
          "r"(b[0]), "r"(b[1]));
}

__device__ __forceinline__ void cp16(uint32_t* smem_dst, const float* gsrc) {
    uint32_t s = (uint32_t)__cvta_generic_to_shared(smem_dst);
    asm volatile("cp.async.ca.shared.global [%0], [%1], 16;\n" :: "r"(s), "l"(gsrc));
}

// =====================================================================
// Kernel 0: prep — gather pooled x (rounded), round weights.
// All sizes in float4 units.
// =====================================================================
#define PREP_N1 (BATCH*NP*(C/4))      // 1204224
#define PREP_N2 (3*C*(C/4))           // 110592
#define PREP_N3 (C*(C/4))             // 36864
__global__ __launch_bounds__(256) void prep_kernel(
    const float* __restrict__ x, const float* __restrict__ qkv_w,
    const float* __restrict__ proj_w)
{
    const int idx = blockIdx.x * 256 + threadIdx.x;
    if (idx < PREP_N1) {
        const int m  = idx / (C/4);
        const int k  = (idx - m * (C/4)) * 4;
        const int b  = m / NP;
        const int i  = m - b * NP;
        const int hi = (i / PW) * SRR;
        const int wi = (i - (i / PW) * PW) * SRR;
        float4 v = *(const float4*)(x + ((size_t)b * NPIX + hi * WW + wi) * C + k);
        v.x = f2tf_f(v.x); v.y = f2tf_f(v.y); v.z = f2tf_f(v.z); v.w = f2tf_f(v.w);
        *(float4*)(g_xp + (size_t)m * C + k) = v;
    } else if (idx < PREP_N1 + PREP_N2) {
        const int e = (idx - PREP_N1) * 4;
        float4 v = *(const float4*)(qkv_w + e);
        v.x = f2tf_f(v.x); v.y = f2tf_f(v.y); v.z = f2tf_f(v.z); v.w = f2tf_f(v.w);
        *(float4*)(g_wq + e) = v;
    } else if (idx < PREP_N1 + PREP_N2 + PREP_N3) {
        const int e = (idx - PREP_N1 - PREP_N2) * 4;
        float4 v = *(const float4*)(proj_w + e);
        v.x = f2tf_f(v.x); v.y = f2tf_f(v.y); v.z = f2tf_f(v.z); v.w = f2tf_f(v.w);
        *(float4*)(g_wp + e) = v;
    }
}

// =====================================================================
// Shared GEMM mainloop: 128x128 block tile, BK=32, 256 threads,
// cp.async double-buffered. A,B row-major with pitch C(=384),
// both pre-rounded to tf32. Warp tile 32(m) x 64(n).
// =====================================================================
#define LDP 36                      // padded row stride in words
#define STAGE_WORDS (128*LDP)       // 4608 words / tile

__device__ __forceinline__ void gemm_mainloop(
    const float* __restrict__ Arows, const float* __restrict__ Brows,
    uint32_t* As, uint32_t* Bs,     // each [2][STAGE_WORDS]
    float acc[2][8][4],
    int warp_m, int warp_n, int gid, int t4, int tid)
{
    const int rbase = tid >> 3;       // 0..31
    const int cchunk = (tid & 7) * 4; // word offset of 16B chunk

    // prologue: stage 0
    #pragma unroll
    for (int t = 0; t < 4; t++) {
        const int r = rbase + t * 32;
        cp16(As + r * LDP + cchunk, Arows + (size_t)r * C + cchunk);
        cp16(Bs + r * LDP + cchunk, Brows + (size_t)r * C + cchunk);
    }
    asm volatile("cp.async.commit_group;\n");

    int buf = 0;
    #pragma unroll 1
    for (int it = 0; it < C / 32; it++) {
        if (it + 1 < C / 32) {
            const int k0 = (it + 1) * 32;
            uint32_t* Ad = As + (buf ^ 1) * STAGE_WORDS;
            uint32_t* Bd = Bs + (buf ^ 1) * STAGE_WORDS;
            #pragma unroll
            for (int t = 0; t < 4; t++) {
                const int r = rbase + t * 32;
                cp16(Ad + r * LDP + cchunk, Arows + (size_t)r * C + k0 + cchunk);
                cp16(Bd + r * LDP + cchunk, Brows + (size_t)r * C + k0 + cchunk);
            }
            asm volatile("cp.async.commit_group;\n");
            asm volatile("cp.async.wait_group 1;\n");
        } else {
            asm volatile("cp.async.wait_group 0;\n");
        }
        __syncthreads();

        const uint32_t* Ac = As + buf * STAGE_WORDS;
        const uint32_t* Bc = Bs + buf * STAGE_WORDS;
        #pragma unroll
        for (int ks = 0; ks < 32; ks += 8) {
            uint32_t af[2][4], bf[8][2];
            #pragma unroll
            for (int i = 0; i < 2; i++) {
                const int r0 = warp_m + i * 16 + gid;
                af[i][0] = Ac[r0 * LDP + ks + t4];
                af[i][1] = Ac[(r0 + 8) * LDP + ks + t4];
                af[i][2] = Ac[r0 * LDP + ks + t4 + 4];
                af[i][3] = Ac[(r0 + 8) * LDP + ks + t4 + 4];
            }
            #pragma unroll
            for (int j = 0; j < 8; j++) {
                const int cc = warp_n + j * 8 + gid;
                bf[j][0] = Bc[cc * LDP + ks + t4];
                bf[j][1] = Bc[cc * LDP + ks + t4 + 4];
            }
            #pragma unroll
            for (int i = 0; i < 2; i++)
                #pragma unroll
                for (int j = 0; j < 8; j++)
                    mma_tf32(acc[i][j], af[i], bf[j]);
        }
        __syncthreads();
        buf ^= 1;
    }
}

// =====================================================================
// Kernel 1: QKV GEMM.  A = g_xp (compact pooled rows), B = g_wq.
// =====================================================================
__global__ __launch_bounds__(256) void qkv_gemm_tf32(const float* __restrict__ bias)
{
    __shared__ uint32_t As[2 * STAGE_WORDS];
    __shared__ uint32_t Bs[2 * STAGE_WORDS];

    const int tile_m = blockIdx.y * 128;
    const int tile_n = blockIdx.x * 128;
    const int tid  = threadIdx.x;
    const int wid  = tid >> 5;
    const int lane = tid & 31;
    const int gid  = lane >> 2;
    const int t4   = lane & 3;
    const int warp_m = (wid & 3) * 32;
    const int warp_n = (wid >> 2) * 64;

    float acc[2][8][4] = {};
    gemm_mainloop(g_xp + (size_t)tile_m * C, g_wq + (size_t)tile_n * C,
                  As, Bs, acc, warp_m, warp_n, gid, t4, tid);

    #pragma unroll
    for (int i = 0; i < 2; i++) {
        #pragma unroll
        for (int half = 0; half < 2; half++) {
            const int gm = tile_m + warp_m + i * 16 + gid + half * 8;
            const int ob = gm / NP;
            const int oi = gm - ob * NP;
            #pragma unroll
            for (int j = 0; j < 8; j++) {
                #pragma unroll
                for (int e = 0; e < 2; e++) {
                    const int gj = tile_n + warp_n + j * 8 + 2 * t4 + e;
                    const float val = acc[i][j][half * 2 + e] + bias[gj];
                    const int which = gj / C;
                    const int c2    = gj - which * C;
                    const int head  = c2 / HD;
                    const int d     = c2 - head * HD;
                    const size_t idx = ((size_t)(ob * HEADS + head) * NP + oi) * HD + d;
                    if (which == 0)      g_q[idx] = val;
                    else if (which == 1) g_k[idx] = val;
                    else                 g_v[idx] = val;
                }
            }
        }
    }
}

// =====================================================================
// Kernel 4: proj GEMM.  A = g_y (pre-rounded), B = g_wp.
// =====================================================================
__global__ __launch_bounds__(256) void proj_gemm_tf32(
    const float* __restrict__ bias, float* __restrict__ out)
{
    __shared__ uint32_t As[2 * STAGE_WORDS];
    __shared__ uint32_t Bs[2 * STAGE_WORDS];

    const int tile_m = blockIdx.y * 128;
    const int tile_n = blockIdx.x * 128;
    const int tid  = threadIdx.x;
    const int wid  = tid >> 5;
    const int lane = tid & 31;
    const int gid  = lane >> 2;
    const int t4   = lane & 3;
    const int warp_m = (wid & 3) * 32;
    const int warp_n = (wid >> 2) * 64;

    float acc[2][8][4] = {};
    gemm_mainloop(g_y + (size_t)tile_m * C, g_wp + (size_t)tile_n * C,
                  As, Bs, acc, warp_m, warp_n, gid, t4, tid);

    #pragma unroll
    for (int i = 0; i < 2; i++) {
        #pragma unroll
        for (int half = 0; half < 2; half++) {
            const int gm = tile_m + warp_m + i * 16 + gid + half * 8;
            #pragma unroll
            for (int j = 0; j < 8; j++) {
                const int gj = tile_n + warp_n + j * 8 + 2 * t4;
                float2 v;
                v.x = acc[i][j][half * 2 + 0] + bias[gj];
                v.y = acc[i][j][half * 2 + 1] + bias[gj + 1];
                *(float2*)(out + (size_t)gm * C + gj) = v;
            }
        }
    }
}

// =====================================================================
// Kernel 2: flash attention, tf32 mma (unchanged from round 3).
// =====================================================================
#define QB 112
#define KB 56
#define ATHREADS 224
#define KSTRIDE 52
#define VSTRIDE 60

__global__ __launch_bounds__(ATHREADS, 2) void attn_mma(float* __restrict__ o_out)
{
    __shared__ uint32_t Ks[KB][KSTRIDE];
    __shared__ uint32_t Vst[HD][VSTRIDE];

    const int bh = blockIdx.y;
    const int qbase = blockIdx.x * QB;
    const int tid  = threadIdx.x;
    const int w    = tid >> 5;
    const int lane = tid & 31;
    const int gid  = lane >> 2;
    const int t4   = lane & 3;

    const float* kbp = g_k + (size_t)bh * NP * HD;
    const float* vbp = g_v + (size_t)bh * NP * HD;

    uint32_t qa[6][4];
    {
        const float* q0 = g_q + ((size_t)bh * NP + qbase + w * 16 + gid) * HD;
        const float* q1 = q0 + 8 * HD;
        #pragma unroll
        for (int ks = 0; ks < 6; ks++) {
            qa[ks][0] = f2tf(SCALE * q0[ks * 8 + t4]);
            qa[ks][1] = f2tf(SCALE * q1[ks * 8 + t4]);
            qa[ks][2] = f2tf(SCALE * q0[ks * 8 + t4 + 4]);
            qa[ks][3] = f2tf(SCALE * q1[ks * 8 + t4 + 4]);
        }
    }

    float m0 = -1e30f, m1 = -1e30f, l0 = 0.f, l1 = 0.f;
    float oacc[6][4] = {};

    for (int kt = 0; kt < NP / KB; kt++) {
        __syncthreads();
        for (int idx = tid; idx < KB * (HD / 4); idx += ATHREADS) {
            const int key = idx / (HD / 4);
            const int d4  = (idx - key * (HD / 4)) * 4;
            const size_t goff = (size_t)(kt * KB + key) * HD + d4;
            float4 kv = *(const float4*)(kbp + goff);
            Ks[key][d4 + 0] = f2tf(kv.x); Ks[key][d4 + 1] = f2tf(kv.y);
            Ks[key][d4 + 2] = f2tf(kv.z); Ks[key][d4 + 3] = f2tf(kv.w);
            float4 vv = *(const float4*)(vbp + goff);
            Vst[d4 + 0][key] = f2tf(vv.x); Vst[d4 + 1][key] = f2tf(vv.y);
            Vst[d4 + 2][key] = f2tf(vv.z); Vst[d4 + 3][key] = f2tf(vv.w);
        }
        __syncthreads();

        float s[7][4] = {};
        #pragma unroll
        for (int j = 0; j < 7; j++) {
            #pragma unroll
            for (int ks = 0; ks < 6; ks++) {
                uint32_t bfr[2];
                bfr[0] = Ks[j * 8 + gid][ks * 8 + t4];
                bfr[1] = Ks[j * 8 + gid][ks * 8 + t4 + 4];
                mma_tf32(s[j], qa[ks], bfr);
            }
        }

        float mx0 = -1e30f, mx1 = -1e30f;
        #pragma unroll
        for (int j = 0; j < 7; j++) {
            mx0 = fmaxf(mx0, fmaxf(s[j][0], s[j][1]));
            mx1 = fmaxf(mx1, fmaxf(s[j][2], s[j][3]));
        }
        mx0 = fmaxf(mx0, __shfl_xor_sync(0xffffffffu, mx0, 1));
        mx0 = fmaxf(mx0, __shfl_xor_sync(0xffffffffu, mx0, 2));
        mx1 = fmaxf(mx1, __shfl_xor_sync(0xffffffffu, mx1, 1));
        mx1 = fmaxf(mx1, __shfl_xor_sync(0xffffffffu, mx1, 2));
        const float nm0 = fmaxf(m0, mx0);
        const float nm1 = fmaxf(m1, mx1);
        const float c0 = __expf(m0 - nm0);
        const float c1 = __expf(m1 - nm1);
        m0 = nm0; m1 = nm1;

        float ps0 = 0.f, ps1 = 0.f;
        #pragma unroll
        for (int j = 0; j < 7; j++) {
            s[j][0] = __expf(s[j][0] - nm0); ps0 += s[j][0];
            s[j][1] = __expf(s[j][1] - nm0); ps0 += s[j][1];
            s[j][2] = __expf(s[j][2] - nm1); ps1 += s[j][2];
            s[j][3] = __expf(s[j][3] - nm1); ps1 += s[j][3];
        }
        ps0 += __shfl_xor_sync(0xffffffffu, ps0, 1);
        ps0 += __shfl_xor_sync(0xffffffffu, ps0, 2);
        ps1 += __shfl_xor_sync(0xffffffffu, ps1, 1);
        ps1 += __shfl_xor_sync(0xffffffffu, ps1, 2);
        l0 = l0 * c0 + ps0;
        l1 = l1 * c1 + ps1;

        #pragma unroll
        for (int n = 0; n < 6; n++) {
            oacc[n][0] *= c0; oacc[n][1] *= c0;
            oacc[n][2] *= c1; oacc[n][3] *= c1;
        }

        const int srcl = (lane & ~3) | (t4 >> 1);
        const bool odd = (t4 & 1);
        #pragma unroll
        for (int j = 0; j < 7; j++) {
            float v00 = __shfl_sync(0xffffffffu, s[j][0], srcl);
            float v01 = __shfl_sync(0xffffffffu, s[j][1], srcl);
            float v20 = __shfl_sync(0xffffffffu, s[j][2], srcl);
            float v21 = __shfl_sync(0xffffffffu, s[j][3], srcl);
            float v40 = __shfl_sync(0xffffffffu, s[j][0], srcl + 2);
            float v41 = __shfl_sync(0xffffffffu, s[j][1], srcl + 2);
            float v60 = __shfl_sync(0xffffffffu, s[j][2], srcl + 2);
            float v61 = __shfl_sync(0xffffffffu, s[j][3], srcl + 2);
            uint32_t a[4];
            a[0] = f2tf(odd ? v01 : v00);
            a[1] = f2tf(odd ? v21 : v20);
            a[2] = f2tf(odd ? v41 : v40);
            a[3] = f2tf(odd ? v61 : v60);
            #pragma unroll
            for (int n = 0; n < 6; n++) {
                uint32_t bfr[2];
                bfr[0] = Vst[n * 8 + gid][j * 8 + t4];
                bfr[1] = Vst[n * 8 + gid][j * 8 + t4 + 4];
                mma_tf32(oacc[n], a, bfr);
            }
        }
    }

    const int b = bh >> 3, head = bh & 7;
    const int q0r = qbase + w * 16 + gid;
    const float inv0 = 1.f / l0;
    const float inv1 = 1.f / l1;
    float* od0 = o_out + ((size_t)b * NP + q0r) * C + head * HD;
    float* od1 = od0 + (size_t)8 * C;
    #pragma unroll
    for (int n = 0; n < 6; n++) {
        const int col = n * 8 + 2 * t4;
        float2 r0; r0.x = oacc[n][0] * inv0; r0.y = oacc[n][1] * inv0;
        float2 r1; r1.x = oacc[n][2] * inv1; r1.y = oacc[n][3] * inv1;
        *(float2*)(od0 + col) = r0;
        *(float2*)(od1 + col) = r1;
    }
}

// =====================================================================
// Kernel 3: upsample + bias + LN, 2x2 quad per block (one pooled pixel).
// Stores tf32-rounded y so proj can consume raw.
// =====================================================================
__global__ __launch_bounds__(128) void up_ln_kernel(
    const float* __restrict__ lp_w, const float* __restrict__ lp_b,
    const float* __restrict__ ln_w, const float* __restrict__ ln_b)
{
    const int pp0 = blockIdx.x;              // b*784 + hh*28 + ww
    const int b   = pp0 / NP;
    const int p2  = pp0 - b * NP;
    const int hh  = p2 / PW;
    const int ww  = p2 - hh * PW;
    const float* orow = g_o + (size_t)pp0 * C;

    const int tid = threadIdx.x;
    float ov[3], lb[3], lw[3], lnbv[3];
    float4 w4[3];
    #pragma unroll
    for (int r = 0; r < 3; r++) {
        const int c = tid + r * 128;
        ov[r] = orow[c];
        w4[r] = *(const float4*)(lp_w + c * 4);
        lb[r] = lp_b[c];
        lw[r] = ln_w[c];
        lnbv[r] = ln_b[c];
    }

    float s[4] = {}, s2[4] = {};
    #pragma unroll
    for (int r = 0; r < 3; r++) {
        const float v0 = ov[r] * w4[r].x + lb[r];
        const float v1 = ov[r] * w4[r].y + lb[r];
        const float v2 = ov[r] * w4[r].z + lb[r];
        const float v3 = ov[r] * w4[r].w + lb[r];
        s[0] += v0; s2[0] += v0 * v0;
        s[1] += v1; s2[1] += v1 * v1;
        s[2] += v2; s2[2] += v2 * v2;
        s[3] += v3; s2[3] += v3 * v3;
    }

    __shared__ float rs[4][4], rs2[4][4];
    #pragma unroll
    for (int pq = 0; pq < 4; pq++) {
        float a = s[pq], a2 = s2[pq];
        #pragma unroll
        for (int off = 16; off > 0; off >>= 1) {
            a  += __shfl_down_sync(0xffffffffu, a,  off);
            a2 += __shfl_down_sync(0xffffffffu, a2, off);
        }
        if ((tid & 31) == 0) { rs[tid >> 5][pq] = a; rs2[tid >> 5][pq] = a2; }
    }
    __syncthreads();

    float mean[4], inv[4];
    #pragma unroll
    for (int pq = 0; pq < 4; pq++) {
        const float S  = rs[0][pq] + rs[1][pq] + rs[2][pq] + rs[3][pq];
        const float S2 = rs2[0][pq] + rs2[1][pq] + rs2[2][pq] + rs2[3][pq];
        mean[pq] = S * (1.f / C);
        const float var = S2 * (1.f / C) - mean[pq] * mean[pq];
        inv[pq] = rsqrtf(var + EPS);
    }

    #pragma unroll
    for (int pq = 0; pq < 4; pq++) {
        const int pp = pq >> 1, qq = pq & 1;
        float* yrow = g_y + ((size_t)b * NPIX + (2 * hh + pp) * WW + (2 * ww + qq)) * C;
        #pragma unroll
        for (int r = 0; r < 3; r++) {
            const int c = tid + r * 128;
            const float wsel = (pq == 0) ? w4[r].x : (pq == 1) ? w4[r].y
                              : (pq == 2) ? w4[r].z : w4[r].w;
            const float val = ov[r] * wsel + lb[r];
            yrow[c] = f2tf_f((val - mean[pq]) * inv[pq] * lw[r] + lnbv[r]);
        }
    }
}

// =====================================================================
// launcher
// =====================================================================
extern "C" void kernel_launch(void* const* d_in, const int* in_sizes, int n_in,
                              void* d_out, int out_size)
{
    const float* x      = (const float*)d_in[0];
    const float* qkv_w  = (const float*)d_in[1];
    const float* qkv_b  = (const float*)d_in[2];
    const float* proj_w = (const float*)d_in[3];
    const float* proj_b = (const float*)d_in[4];
    const float* lp_w   = (const float*)d_in[5];
    const float* lp_b   = (const float*)d_in[6];
    const float* ln_w   = (const float*)d_in[7];
    const float* ln_b   = (const float*)d_in[8];
    float* out = (float*)d_out;

    float* o_ptr = nullptr;
    cudaGetSymbolAddress((void**)&o_ptr, g_o);

    // 0) prep: pooled-x gather + weight rounding
    {
        const int total = PREP_N1 + PREP_N2 + PREP_N3;
        prep_kernel<<<(total + 255) / 256, 256>>>(x, qkv_w, proj_w);
    }
    // 1) QKV gemm
    {
        dim3 grid((3 * C) / 128, (BATCH * NP) / 128);
        qkv_gemm_tf32<<<grid, 256>>>(qkv_b);
    }
    // 2) attention
    {
        dim3 grid(NP / QB, BH);
        attn_mma<<<grid, ATHREADS>>>(o_ptr);
    }
    // 3) upsample + LN (quad)
    {
        up_ln_kernel<<<BATCH * NP, 128>>>(lp_w, lp_b, ln_w, ln_b);
    }
    // 4) proj gemm
    {
        dim3 grid(C / 128, (BATCH * NPIX) / 128);
        proj_gemm_tf32<<<grid, 256>>>(proj_b, out);
    }
}

// round 6
// speedup vs baseline: 6.4499x; 1.0373x over previous
#include <cuda_runtime.h>
#include <cstdint>

// ---------------- problem constants ----------------
#define BATCH   16
#define HH      56
#define WW      56
#define NPIX    (HH*WW)        // 3136
#define C       384
#define HEADS   8
#define HD      48
#define SRR     2
#define PH      (HH/SRR)       // 28
#define PW      (WW/SRR)       // 28
#define NP      (PH*PW)        // 784
#define BH      (BATCH*HEADS)  // 128
#define SCALE   0.14433756729740643f  // 48^-0.5
#define EPS     1e-5f

// ---------------- scratch ----------------
__device__ float g_q[(size_t)BH * NP * HD];               // tf32(SCALE*q)
__device__ float g_k[(size_t)BH * NP * HD];               // tf32(k)
__device__ float g_vt[(size_t)BH * HD * NP];              // tf32(v), transposed [bh][d][key]
__device__ float g_o[(size_t)BATCH * NP * C];
__device__ float g_y[(size_t)BATCH * NPIX * C];
__device__ float g_xp[(size_t)BATCH * NP * C];            // pooled, tf32-rounded x
__device__ float g_wq[(size_t)3 * C * C];                 // tf32-rounded qkv_w
__device__ float g_wp[(size_t)C * C];                     // tf32-rounded proj_w

// ---------------- tf32 helpers ----------------
__device__ __forceinline__ uint32_t f2tf(float f) {
    uint32_t u;
    asm("cvt.rna.tf32.f32 %0, %1;" : "=r"(u) : "f"(f));
    return u;
}
__device__ __forceinline__ float f2tf_f(float f) {
    return __uint_as_float(f2tf(f));
}

__device__ __forceinline__ void mma_tf32(float* d, const uint32_t* a, const uint32_t* b) {
    asm volatile(
        "mma.sync.aligned.m16n8k8.row.col.f32.tf32.tf32.f32 "
        "{%0,%1,%2,%3}, {%4,%5,%6,%7}, {%8,%9}, {%0,%1,%2,%3};\n"
        : "+f"(d[0]), "+f"(d[1]), "+f"(d[2]), "+f"(d[3])
        : "r"(a[0]), "r"(a[1]), "r"(a[2]), "r"(a[3]),
          "r"(b[0]), "r"(b[1]));
}

__device__ __forceinline__ void cp16(uint32_t* smem_dst, const float* gsrc) {
    uint32_t s = (uint32_t)__cvta_generic_to_shared(smem_dst);
    asm volatile("cp.async.ca.shared.global [%0], [%1], 16;\n" :: "r"(s), "l"(gsrc));
}

// =====================================================================
// Kernel 0: prep — gather pooled x (rounded), round weights.
// =====================================================================
#define PREP_N1 (BATCH*NP*(C/4))
#define PREP_N2 (3*C*(C/4))
#define PREP_N3 (C*(C/4))
__global__ __launch_bounds__(256) void prep_kernel(
    const float* __restrict__ x, const float* __restrict__ qkv_w,
    const float* __restrict__ proj_w)
{
    const int idx = blockIdx.x * 256 + threadIdx.x;
    if (idx < PREP_N1) {
        const int m  = idx / (C/4);
        const int k  = (idx - m * (C/4)) * 4;
        const int b  = m / NP;
        const int i  = m - b * NP;
        const int hi = (i / PW) * SRR;
        const int wi = (i - (i / PW) * PW) * SRR;
        float4 v = *(const float4*)(x + ((size_t)b * NPIX + hi * WW + wi) * C + k);
        v.x = f2tf_f(v.x); v.y = f2tf_f(v.y); v.z = f2tf_f(v.z); v.w = f2tf_f(v.w);
        *(float4*)(g_xp + (size_t)m * C + k) = v;
    } else if (idx < PREP_N1 + PREP_N2) {
        const int e = (idx - PREP_N1) * 4;
        float4 v = *(const float4*)(qkv_w + e);
        v.x = f2tf_f(v.x); v.y = f2tf_f(v.y); v.z = f2tf_f(v.z); v.w = f2tf_f(v.w);
        *(float4*)(g_wq + e) = v;
    } else if (idx < PREP_N1 + PREP_N2 + PREP_N3) {
        const int e = (idx - PREP_N1 - PREP_N2) * 4;
        float4 v = *(const float4*)(proj_w + e);
        v.x = f2tf_f(v.x); v.y = f2tf_f(v.y); v.z = f2tf_f(v.z); v.w = f2tf_f(v.w);
        *(float4*)(g_wp + e) = v;
    }
}

// =====================================================================
// Shared GEMM mainloop: 128x128 block tile, BK=32, 256 threads,
// cp.async double-buffered. Warp tile 32(m) x 64(n).
// =====================================================================
#define LDP 36
#define STAGE_WORDS (128*LDP)

__device__ __forceinline__ void gemm_mainloop(
    const float* __restrict__ Arows, const float* __restrict__ Brows,
    uint32_t* As, uint32_t* Bs,
    float acc[2][8][4],
    int warp_m, int warp_n, int gid, int t4, int tid)
{
    const int rbase = tid >> 3;
    const int cchunk = (tid & 7) * 4;

    #pragma unroll
    for (int t = 0; t < 4; t++) {
        const int r = rbase + t * 32;
        cp16(As + r * LDP + cchunk, Arows + (size_t)r * C + cchunk);
        cp16(Bs + r * LDP + cchunk, Brows + (size_t)r * C + cchunk);
    }
    asm volatile("cp.async.commit_group;\n");

    int buf = 0;
    #pragma unroll 1
    for (int it = 0; it < C / 32; it++) {
        if (it + 1 < C / 32) {
            const int k0 = (it + 1) * 32;
            uint32_t* Ad = As + (buf ^ 1) * STAGE_WORDS;
            uint32_t* Bd = Bs + (buf ^ 1) * STAGE_WORDS;
            #pragma unroll
            for (int t = 0; t < 4; t++) {
                const int r = rbase + t * 32;
                cp16(Ad + r * LDP + cchunk, Arows + (size_t)r * C + k0 + cchunk);
                cp16(Bd + r * LDP + cchunk, Brows + (size_t)r * C + k0 + cchunk);
            }
            asm volatile("cp.async.commit_group;\n");
            asm volatile("cp.async.wait_group 1;\n");
        } else {
            asm volatile("cp.async.wait_group 0;\n");
        }
        __syncthreads();

        const uint32_t* Ac = As + buf * STAGE_WORDS;
        const uint32_t* Bc = Bs + buf * STAGE_WORDS;
        #pragma unroll
        for (int ks = 0; ks < 32; ks += 8) {
            uint32_t af[2][4], bf[8][2];
            #pragma unroll
            for (int i = 0; i < 2; i++) {
                const int r0 = warp_m + i * 16 + gid;
                af[i][0] = Ac[r0 * LDP + ks + t4];
                af[i][1] = Ac[(r0 + 8) * LDP + ks + t4];
                af[i][2] = Ac[r0 * LDP + ks + t4 + 4];
                af[i][3] = Ac[(r0 + 8) * LDP + ks + t4 + 4];
            }
            #pragma unroll
            for (int j = 0; j < 8; j++) {
                const int cc = warp_n + j * 8 + gid;
                bf[j][0] = Bc[cc * LDP + ks + t4];
                bf[j][1] = Bc[cc * LDP + ks + t4 + 4];
            }
            #pragma unroll
            for (int i = 0; i < 2; i++)
                #pragma unroll
                for (int j = 0; j < 8; j++)
                    mma_tf32(acc[i][j], af[i], bf[j]);
        }
        __syncthreads();
        buf ^= 1;
    }
}

// =====================================================================
// Kernel 1: QKV GEMM.  Epilogue pre-rounds q (scaled), k, and writes V
// transposed+rounded for the attention kernel.
// =====================================================================
__global__ __launch_bounds__(256) void qkv_gemm_tf32(const float* __restrict__ bias)
{
    __shared__ uint32_t As[2 * STAGE_WORDS];
    __shared__ uint32_t Bs[2 * STAGE_WORDS];

    const int tile_m = blockIdx.y * 128;
    const int tile_n = blockIdx.x * 128;
    const int tid  = threadIdx.x;
    const int wid  = tid >> 5;
    const int lane = tid & 31;
    const int gid  = lane >> 2;
    const int t4   = lane & 3;
    const int warp_m = (wid & 3) * 32;
    const int warp_n = (wid >> 2) * 64;

    float acc[2][8][4] = {};
    gemm_mainloop(g_xp + (size_t)tile_m * C, g_wq + (size_t)tile_n * C,
                  As, Bs, acc, warp_m, warp_n, gid, t4, tid);

    #pragma unroll
    for (int i = 0; i < 2; i++) {
        #pragma unroll
        for (int half = 0; half < 2; half++) {
            const int gm = tile_m + warp_m + i * 16 + gid + half * 8;
            const int ob = gm / NP;
            const int oi = gm - ob * NP;
            #pragma unroll
            for (int j = 0; j < 8; j++) {
                #pragma unroll
                for (int e = 0; e < 2; e++) {
                    const int gj = tile_n + warp_n + j * 8 + 2 * t4 + e;
                    const float val = acc[i][j][half * 2 + e] + bias[gj];
                    const int which = gj / C;
                    const int c2    = gj - which * C;
                    const int head  = c2 / HD;
                    const int d     = c2 - head * HD;
                    const int bhid  = ob * HEADS + head;
                    if (which == 0)
                        g_q[((size_t)bhid * NP + oi) * HD + d] = f2tf_f(SCALE * val);
                    else if (which == 1)
                        g_k[((size_t)bhid * NP + oi) * HD + d] = f2tf_f(val);
                    else
                        g_vt[((size_t)bhid * HD + d) * NP + oi] = f2tf_f(val);
                }
            }
        }
    }
}

// =====================================================================
// Kernel 4: proj GEMM.
// =====================================================================
__global__ __launch_bounds__(256) void proj_gemm_tf32(
    const float* __restrict__ bias, float* __restrict__ out)
{
    __shared__ uint32_t As[2 * STAGE_WORDS];
    __shared__ uint32_t Bs[2 * STAGE_WORDS];

    const int tile_m = blockIdx.y * 128;
    const int tile_n = blockIdx.x * 128;
    const int tid  = threadIdx.x;
    const int wid  = tid >> 5;
    const int lane = tid & 31;
    const int gid  = lane >> 2;
    const int t4   = lane & 3;
    const int warp_m = (wid & 3) * 32;
    const int warp_n = (wid >> 2) * 64;

    float acc[2][8][4] = {};
    gemm_mainloop(g_y + (size_t)tile_m * C, g_wp + (size_t)tile_n * C,
                  As, Bs, acc, warp_m, warp_n, gid, t4, tid);

    #pragma unroll
    for (int i = 0; i < 2; i++) {
        #pragma unroll
        for (int half = 0; half < 2; half++) {
            const int gm = tile_m + warp_m + i * 16 + gid + half * 8;
            #pragma unroll
            for (int j = 0; j < 8; j++) {
                const int gj = tile_n + warp_n + j * 8 + 2 * t4;
                float2 v;
                v.x = acc[i][j][half * 2 + 0] + bias[gj];
                v.y = acc[i][j][half * 2 + 1] + bias[gj + 1];
                *(float2*)(out + (size_t)gm * C + gj) = v;
            }
        }
    }
}

// =====================================================================
// Kernel 2: flash attention, tf32 mma, cp.async double-buffered KV.
// All inputs pre-rounded (q pre-scaled); no cvt in the tile path.
// =====================================================================
#define QB 112
#define KB 56
#define ATHREADS 224
#define KSTRIDE 52   // words; 208B row pitch, 16B aligned, conflict-free frags
#define VSTRIDE 60   // words; 240B row pitch, 16B aligned, conflict-free frags

__global__ __launch_bounds__(ATHREADS, 2) void attn_mma(float* __restrict__ o_out)
{
    __shared__ uint32_t Ks[2][KB][KSTRIDE];
    __shared__ uint32_t Vst[2][HD][VSTRIDE];

    const int bh = blockIdx.y;
    const int qbase = blockIdx.x * QB;
    const int tid  = threadIdx.x;
    const int w    = tid >> 5;
    const int lane = tid & 31;
    const int gid  = lane >> 2;
    const int t4   = lane & 3;

    const float* kbp = g_k  + (size_t)bh * NP * HD;
    const float* vtp = g_vt + (size_t)bh * HD * NP;

    // Q fragments (already scaled + tf32-rounded)
    uint32_t qa[6][4];
    {
        const uint32_t* q0 = (const uint32_t*)g_q + ((size_t)bh * NP + qbase + w * 16 + gid) * HD;
        const uint32_t* q1 = q0 + 8 * HD;
        #pragma unroll
        for (int ks = 0; ks < 6; ks++) {
            qa[ks][0] = q0[ks * 8 + t4];
            qa[ks][1] = q1[ks * 8 + t4];
            qa[ks][2] = q0[ks * 8 + t4 + 4];
            qa[ks][3] = q1[ks * 8 + t4 + 4];
        }
    }

    // tile loader: K rows 56 x 12 chunks, V rows 48 x 14 chunks
    auto load_tile = [&](int kt, int bufi) {
        #pragma unroll
        for (int r = 0; r < 3; r++) {
            const int idx = tid + r * ATHREADS;        // 0..671
            const int row = idx / 12;
            const int c   = (idx - row * 12) * 4;
            cp16(&Ks[bufi][row][c], kbp + (size_t)(kt * KB + row) * HD + c);
        }
        #pragma unroll
        for (int r = 0; r < 3; r++) {
            const int idx = tid + r * ATHREADS;
            const int row = idx / 14;
            const int c   = (idx - row * 14) * 4;
            cp16(&Vst[bufi][row][c], vtp + (size_t)row * NP + kt * KB + c);
        }
        asm volatile("cp.async.commit_group;\n");
    };

    float m0 = -1e30f, m1 = -1e30f, l0 = 0.f, l1 = 0.f;
    float oacc[6][4] = {};

    load_tile(0, 0);
    int buf = 0;

    #pragma unroll 1
    for (int kt = 0; kt < NP / KB; kt++) {
        if (kt + 1 < NP / KB) {
            load_tile(kt + 1, buf ^ 1);
            asm volatile("cp.async.wait_group 1;\n");
        } else {
            asm volatile("cp.async.wait_group 0;\n");
        }
        __syncthreads();

        // S = Qs @ K^T
        float s[7][4] = {};
        #pragma unroll
        for (int j = 0; j < 7; j++) {
            #pragma unroll
            for (int ks = 0; ks < 6; ks++) {
                uint32_t bfr[2];
                bfr[0] = Ks[buf][j * 8 + gid][ks * 8 + t4];
                bfr[1] = Ks[buf][j * 8 + gid][ks * 8 + t4 + 4];
                mma_tf32(s[j], qa[ks], bfr);
            }
        }

        // online softmax
        float mx0 = -1e30f, mx1 = -1e30f;
        #pragma unroll
        for (int j = 0; j < 7; j++) {
            mx0 = fmaxf(mx0, fmaxf(s[j][0], s[j][1]));
            mx1 = fmaxf(mx1, fmaxf(s[j][2], s[j][3]));
        }
        mx0 = fmaxf(mx0, __shfl_xor_sync(0xffffffffu, mx0, 1));
        mx0 = fmaxf(mx0, __shfl_xor_sync(0xffffffffu, mx0, 2));
        mx1 = fmaxf(mx1, __shfl_xor_sync(0xffffffffu, mx1, 1));
        mx1 = fmaxf(mx1, __shfl_xor_sync(0xffffffffu, mx1, 2));
        const float nm0 = fmaxf(m0, mx0);
        const float nm1 = fmaxf(m1, mx1);
        const float c0 = __expf(m0 - nm0);
        const float c1 = __expf(m1 - nm1);
        m0 = nm0; m1 = nm1;

        float ps0 = 0.f, ps1 = 0.f;
        #pragma unroll
        for (int j = 0; j < 7; j++) {
            s[j][0] = __expf(s[j][0] - nm0); ps0 += s[j][0];
            s[j][1] = __expf(s[j][1] - nm0); ps0 += s[j][1];
            s[j][2] = __expf(s[j][2] - nm1); ps1 += s[j][2];
            s[j][3] = __expf(s[j][3] - nm1); ps1 += s[j][3];
        }
        ps0 += __shfl_xor_sync(0xffffffffu, ps0, 1);
        ps0 += __shfl_xor_sync(0xffffffffu, ps0, 2);
        ps1 += __shfl_xor_sync(0xffffffffu, ps1, 1);
        ps1 += __shfl_xor_sync(0xffffffffu, ps1, 2);
        l0 = l0 * c0 + ps0;
        l1 = l1 * c1 + ps1;

        #pragma unroll
        for (int n = 0; n < 6; n++) {
            oacc[n][0] *= c0; oacc[n][1] *= c0;
            oacc[n][2] *= c1; oacc[n][3] *= c1;
        }

        // O += P @ V  (C-frag -> A-frag via shuffles)
        const int srcl = (lane & ~3) | (t4 >> 1);
        const bool odd = (t4 & 1);
        #pragma unroll
        for (int j = 0; j < 7; j++) {
            float v00 = __shfl_sync(0xffffffffu, s[j][0], srcl);
            float v01 = __shfl_sync(0xffffffffu, s[j][1], srcl);
            float v20 = __shfl_sync(0xffffffffu, s[j][2], srcl);
            float v21 = __shfl_sync(0xffffffffu, s[j][3], srcl);
            float v40 = __shfl_sync(0xffffffffu, s[j][0], srcl + 2);
            float v41 = __shfl_sync(0xffffffffu, s[j][1], srcl + 2);
            float v60 = __shfl_sync(0xffffffffu, s[j][2], srcl + 2);
            float v61 = __shfl_sync(0xffffffffu, s[j][3], srcl + 2);
            uint32_t a[4];
            a[0] = f2tf(odd ? v01 : v00);
            a[1] = f2tf(odd ? v21 : v20);
            a[2] = f2tf(odd ? v41 : v40);
            a[3] = f2tf(odd ? v61 : v60);
            #pragma unroll
            for (int n = 0; n < 6; n++) {
                uint32_t bfr[2];
                bfr[0] = Vst[buf][n * 8 + gid][j * 8 + t4];
                bfr[1] = Vst[buf][n * 8 + gid][j * 8 + t4 + 4];
                mma_tf32(oacc[n], a, bfr);
            }
        }
        __syncthreads();
        buf ^= 1;
    }

    const int b = bh >> 3, head = bh & 7;
    const int q0r = qbase + w * 16 + gid;
    const float inv0 = 1.f / l0;
    const float inv1 = 1.f / l1;
    float* od0 = o_out + ((size_t)b * NP + q0r) * C + head * HD;
    float* od1 = od0 + (size_t)8 * C;
    #pragma unroll
    for (int n = 0; n < 6; n++) {
        const int col = n * 8 + 2 * t4;
        float2 r0; r0.x = oacc[n][0] * inv0; r0.y = oacc[n][1] * inv0;
        float2 r1; r1.x = oacc[n][2] * inv1; r1.y = oacc[n][3] * inv1;
        *(float2*)(od0 + col) = r0;
        *(float2*)(od1 + col) = r1;
    }
}

// =====================================================================
// Kernel 3: upsample + bias + LN, 2x2 quad per block.
// =====================================================================
__global__ __launch_bounds__(128) void up_ln_kernel(
    const float* __restrict__ lp_w, const float* __restrict__ lp_b,
    const float* __restrict__ ln_w, const float* __restrict__ ln_b)
{
    const int pp0 = blockIdx.x;
    const int b   = pp0 / NP;
    const int p2  = pp0 - b * NP;
    const int hh  = p2 / PW;
    const int ww  = p2 - hh * PW;
    const float* orow = g_o + (size_t)pp0 * C;

    const int tid = threadIdx.x;
    float ov[3], lb[3], lw[3], lnbv[3];
    float4 w4[3];
    #pragma unroll
    for (int r = 0; r < 3; r++) {
        const int c = tid + r * 128;
        ov[r] = orow[c];
        w4[r] = *(const float4*)(lp_w + c * 4);
        lb[r] = lp_b[c];
        lw[r] = ln_w[c];
        lnbv[r] = ln_b[c];
    }

    float s[4] = {}, s2[4] = {};
    #pragma unroll
    for (int r = 0; r < 3; r++) {
        const float v0 = ov[r] * w4[r].x + lb[r];
        const float v1 = ov[r] * w4[r].y + lb[r];
        const float v2 = ov[r] * w4[r].z + lb[r];
        const float v3 = ov[r] * w4[r].w + lb[r];
        s[0] += v0; s2[0] += v0 * v0;
        s[1] += v1; s2[1] += v1 * v1;
        s[2] += v2; s2[2] += v2 * v2;
        s[3] += v3; s2[3] += v3 * v3;
    }

    __shared__ float rs[4][4], rs2[4][4];
    #pragma unroll
    for (int pq = 0; pq < 4; pq++) {
        float a = s[pq], a2 = s2[pq];
        #pragma unroll
        for (int off = 16; off > 0; off >>= 1) {
            a  += __shfl_down_sync(0xffffffffu, a,  off);
            a2 += __shfl_down_sync(0xffffffffu, a2, off);
        }
        if ((tid & 31) == 0) { rs[tid >> 5][pq] = a; rs2[tid >> 5][pq] = a2; }
    }
    __syncthreads();

    float mean[4], inv[4];
    #pragma unroll
    for (int pq = 0; pq < 4; pq++) {
        const float S  = rs[0][pq] + rs[1][pq] + rs[2][pq] + rs[3][pq];
        const float S2 = rs2[0][pq] + rs2[1][pq] + rs2[2][pq] + rs2[3][pq];
        mean[pq] = S * (1.f / C);
        const float var = S2 * (1.f / C) - mean[pq] * mean[pq];
        inv[pq] = rsqrtf(var + EPS);
    }

    #pragma unroll
    for (int pq = 0; pq < 4; pq++) {
        const int pp = pq >> 1, qq = pq & 1;
        float* yrow = g_y + ((size_t)b * NPIX + (2 * hh + pp) * WW + (2 * ww + qq)) * C;
        #pragma unroll
        for (int r = 0; r < 3; r++) {
            const int c = tid + r * 128;
            const float wsel = (pq == 0) ? w4[r].x : (pq == 1) ? w4[r].y
                              : (pq == 2) ? w4[r].z : w4[r].w;
            const float val = ov[r] * wsel + lb[r];
            yrow[c] = f2tf_f((val - mean[pq]) * inv[pq] * lw[r] + lnbv[r]);
        }
    }
}

// =====================================================================
// launcher
// =====================================================================
extern "C" void kernel_launch(void* const* d_in, const int* in_sizes, int n_in,
                              void* d_out, int out_size)
{
    const float* x      = (const float*)d_in[0];
    const float* qkv_w  = (const float*)d_in[1];
    const float* qkv_b  = (const float*)d_in[2];
    const float* proj_w = (const float*)d_in[3];
    const float* proj_b = (const float*)d_in[4];
    const float* lp_w   = (const float*)d_in[5];
    const float* lp_b   = (const float*)d_in[6];
    const float* ln_w   = (const float*)d_in[7];
    const float* ln_b   = (const float*)d_in[8];
    float* out = (float*)d_out;

    float* o_ptr = nullptr;
    cudaGetSymbolAddress((void**)&o_ptr, g_o);

    // 0) prep
    {
        const int total = PREP_N1 + PREP_N2 + PREP_N3;
        prep_kernel<<<(total + 255) / 256, 256>>>(x, qkv_w, proj_w);
    }
    // 1) QKV gemm
    {
        dim3 grid((3 * C) / 128, (BATCH * NP) / 128);
        qkv_gemm_tf32<<<grid, 256>>>(qkv_b);
    }
    // 2) attention
    {
        dim3 grid(NP / QB, BH);
        attn_mma<<<grid, ATHREADS>>>(o_ptr);
    }
    // 3) upsample + LN
    {
        up_ln_kernel<<<BATCH * NP, 128>>>(lp_w, lp_b, ln_w, ln_b);
    }
    // 4) proj gemm
    {
        dim3 grid(C / 128, (BATCH * NPIX) / 128);
        proj_gemm_tf32<<<grid, 256>>>(proj_b, out);
    }
}